// round 14
// baseline (speedup 1.0000x reference)
#include <cuda_runtime.h>
#include <cuda_fp16.h>
#include <cstdint>

// ---------------------------------------------------------------------------
// Problem constants
// ---------------------------------------------------------------------------
#define DIN   4096
#define DOUT  4096
#define MTOT  8192
#define BK    64                          // fp16 k-elems per chunk (128 B/row)
#define NCHUNK (DIN / BK)                 // 64 — single fp16 pass
#define BM    256
#define BN    128
#define NTHREADS 512
#define NSTAGE 4
#define A_BYTES  32768                    // 256 rows x 128 B
#define B_BYTES  16384                    // 128 rows x 128 B
#define STAGE_BYTES (A_BYTES + B_BYTES)   // 48 KB
#define SMEM_TOTAL (NSTAGE * STAGE_BYTES) // 192 KB
static __device__ __constant__ float kScaling = 2.0f;   // 32 / rank(16)

// ---------------------------------------------------------------------------
// Device-global scratch
// ---------------------------------------------------------------------------
__device__ __half g_Xh[(size_t)MTOT * DIN];   // fp16(x)
__device__ __half g_Wh[(size_t)DOUT * DIN];   // fp16(W_eff)

// ---------------------------------------------------------------------------
// Helpers (baseline PTX only — compiles at compute_103)
// ---------------------------------------------------------------------------
__device__ __forceinline__ uint32_t smem_u32(const void* p) {
    uint32_t a;
    asm("{ .reg .u64 t; cvta.to.shared.u64 t, %1; cvt.u32.u64 %0, t; }" : "=r"(a) : "l"(p));
    return a;
}
__device__ __forceinline__ void cp_async16(uint32_t dst, const void* src) {
    asm volatile("cp.async.cg.shared.global [%0], [%1], 16;"
                 :: "r"(dst), "l"(__cvta_generic_to_global(src)));
}
#define CP_COMMIT() asm volatile("cp.async.commit_group;" ::: "memory")
#define CP_WAIT(n)  asm volatile("cp.async.wait_group %0;" :: "n"(n) : "memory")

__device__ __forceinline__ uint32_t swz(uint32_t o) { return o ^ ((o >> 3) & 0x70); }

__device__ __forceinline__ void ldsm_x4(uint32_t* r, uint32_t addr) {
    asm volatile("ldmatrix.sync.aligned.m8n8.x4.shared.b16 {%0,%1,%2,%3}, [%4];"
                 : "=r"(r[0]), "=r"(r[1]), "=r"(r[2]), "=r"(r[3]) : "r"(addr));
}
__device__ __forceinline__ void mma_fp16(float* c, const uint32_t* a,
                                         uint32_t b0, uint32_t b1) {
    asm volatile(
        "mma.sync.aligned.m16n8k16.row.col.f32.f16.f16.f32 "
        "{%0,%1,%2,%3}, {%4,%5,%6,%7}, {%8,%9}, {%0,%1,%2,%3};"
        : "+f"(c[0]), "+f"(c[1]), "+f"(c[2]), "+f"(c[3])
        : "r"(a[0]), "r"(a[1]), "r"(a[2]), "r"(a[3]), "r"(b0), "r"(b1));
}

// ---------------------------------------------------------------------------
// Fused prologue with IN-KERNEL mask dtype detection (unchanged from R13):
//   blocks [0, 4096)     : fold row o — W_eff = W + delta*mask + 2*(B@A) → fp16
//   blocks [4096, 8192)  : convert 2 rows of X → fp16
// Each fold block classifies the mask dtype from a fixed 8KB prefix
// (2048 words; P(all-zero | 1% density) ≈ 1e-9; 8KB << min 16MB buffer).
// ---------------------------------------------------------------------------
__global__ void prep_kernel(const float* __restrict__ W,
                            const float* __restrict__ lora_A,
                            const float* __restrict__ lora_B,
                            const float* __restrict__ delta,
                            const void*  __restrict__ maskp,
                            const float* __restrict__ x) {
    if (blockIdx.x < DOUT) {
        const int o = blockIdx.x;
        __shared__ float br[16];
        __shared__ int s_flags[2];
        if (threadIdx.x < 2) s_flags[threadIdx.x] = 0;
        if (threadIdx.x < 16) br[threadIdx.x] = lora_B[o * 16 + threadIdx.x] * kScaling;
        __syncthreads();

        {
            const unsigned int* mw = (const unsigned int*)maskp;
            int notF = 0, notI = 0;
#pragma unroll
            for (int it = 0; it < 8; it++) {
                unsigned int v = mw[it * 256 + threadIdx.x];
                if (v != 0u && v != 0x3F800000u) notF = 1;
                if (v > 1u)                       notI = 1;
            }
            notF = __any_sync(0xFFFFFFFFu, notF);
            notI = __any_sync(0xFFFFFFFFu, notI);
            if ((threadIdx.x & 31) == 0) {
                if (notF) atomicOr(&s_flags[0], 1);
                if (notI) atomicOr(&s_flags[1], 1);
            }
        }
        __syncthreads();
        const int mode = (s_flags[0] == 0) ? 0 : ((s_flags[1] == 0) ? 1 : 2);
        const size_t rowoff = (size_t)o * DIN;

        for (int d = threadIdx.x * 4; d < DIN; d += blockDim.x * 4) {
            float4 w4 = *(const float4*)(W + rowoff + d);
            float4 dl = *(const float4*)(delta + rowoff + d);

            float m0, m1, m2, m3;
            if (mode == 0) {
                float4 mf = *(const float4*)((const float*)maskp + rowoff + d);
                m0 = mf.x; m1 = mf.y; m2 = mf.z; m3 = mf.w;
            } else if (mode == 1) {
                int4 mi = *(const int4*)((const int*)maskp + rowoff + d);
                m0 = mi.x ? 1.f : 0.f; m1 = mi.y ? 1.f : 0.f;
                m2 = mi.z ? 1.f : 0.f; m3 = mi.w ? 1.f : 0.f;
            } else {
                uchar4 mu = *(const uchar4*)((const unsigned char*)maskp + rowoff + d);
                m0 = mu.x ? 1.f : 0.f; m1 = mu.y ? 1.f : 0.f;
                m2 = mu.z ? 1.f : 0.f; m3 = mu.w ? 1.f : 0.f;
            }

            float l0 = 0.f, l1 = 0.f, l2 = 0.f, l3 = 0.f;
#pragma unroll
            for (int r = 0; r < 16; r++) {
                float4 a4 = *(const float4*)(lora_A + (size_t)r * DIN + d);
                float s = br[r];
                l0 = fmaf(s, a4.x, l0); l1 = fmaf(s, a4.y, l1);
                l2 = fmaf(s, a4.z, l2); l3 = fmaf(s, a4.w, l3);
            }

            float v0 = w4.x + dl.x * m0 + l0;
            float v1 = w4.y + dl.y * m1 + l1;
            float v2 = w4.z + dl.z * m2 + l2;
            float v3 = w4.w + dl.w * m3 + l3;

            __half2 h01 = __floats2half2_rn(v0, v1);
            __half2 h23 = __floats2half2_rn(v2, v3);
            uint2 H;
            H.x = *(const uint32_t*)&h01;
            H.y = *(const uint32_t*)&h23;
            *(uint2*)((char*)g_Wh + (rowoff + d) * 2) = H;
        }
    } else {
        const size_t rowbase = (size_t)(blockIdx.x - DOUT) * 2 * DIN;
#pragma unroll
        for (int it = 0; it < 4; it++) {
            size_t base = rowbase + ((size_t)it * blockDim.x + threadIdx.x) * 8;
            float4 a = *(const float4*)(x + base);
            float4 b = *(const float4*)(x + base + 4);
            __half2 h0 = __floats2half2_rn(a.x, a.y);
            __half2 h1 = __floats2half2_rn(a.z, a.w);
            __half2 h2 = __floats2half2_rn(b.x, b.y);
            __half2 h3 = __floats2half2_rn(b.z, b.w);
            uint4 H;
            H.x = *(const uint32_t*)&h0; H.y = *(const uint32_t*)&h1;
            H.z = *(const uint32_t*)&h2; H.w = *(const uint32_t*)&h3;
            *(uint4*)((char*)g_Xh + base * 2) = H;
        }
    }
}

// ---------------------------------------------------------------------------
// fp16 HMMA GEMM: out[256x128 tile] = Xh·Wh^T + bias
// 512 threads, 16 warps (4m × 4n), warp tile 64x32, 4-stage cp.async pipe,
// 1 CTA/SM (192 KB smem). Doubled work per barrier vs R13 halves the
// per-chunk sync bubble fraction.
// ---------------------------------------------------------------------------
__global__ __launch_bounds__(NTHREADS, 1)
void gemm_kernel(const float* __restrict__ bias, float* __restrict__ out) {
    extern __shared__ __align__(1024) char smem[];
    const uint32_t sbase = smem_u32(smem);
    const int tid = threadIdx.x;
    const int lane = tid & 31;
    const int wid = tid >> 5;             // 0..15
    const int warpM = wid >> 2;           // 0..3 (64 rows each)
    const int warpN = wid & 3;            // 0..3 (32 cols each)
    const int bm = blockIdx.x * BM;       // m fastest → W stays L2-resident
    const int bn = blockIdx.y * BN;

    // loader mapping: A 4 slots (2048 x 16B), B 2 slots (1024 x 16B)
    int rowLA[4]; uint32_t dstLA[4]; int colLA[4];
#pragma unroll
    for (int i = 0; i < 4; i++) {
        int slot = tid + NTHREADS * i;    // 0..2047
        rowLA[i] = slot >> 3;             // 0..255
        colLA[i] = (slot & 7) * 8;        // fp16 col
        dstLA[i] = swz((uint32_t)(rowLA[i] * 128 + (slot & 7) * 16));
    }
    int rowLB[2]; uint32_t dstLB[2]; int colLB[2];
#pragma unroll
    for (int i = 0; i < 2; i++) {
        int slot = tid + NTHREADS * i;    // 0..1023
        rowLB[i] = slot >> 3;             // 0..127
        colLB[i] = (slot & 7) * 8;
        dstLB[i] = swz((uint32_t)(rowLB[i] * 128 + (slot & 7) * 16));
    }

    // ldmatrix per-lane UNswizzled base offsets; swizzle applied per use
    // on the full offset (R4 lesson: swz does not commute with +ks*32).
    const int arow  = (lane & 7) + ((lane >> 3) & 1) * 8;
    const int acol  = ((lane >> 4) & 1) * 16;           // byte
    const int brow  = (lane & 7) + ((lane >> 4) & 1) * 8;
    const int bcol  = ((lane >> 3) & 1) * 16;           // byte
    uint32_t baseA[4], baseB[2];
#pragma unroll
    for (int mt = 0; mt < 4; mt++)
        baseA[mt] = (uint32_t)((warpM * 64 + mt * 16 + arow) * 128 + acol);
#pragma unroll
    for (int p = 0; p < 2; p++)
        baseB[p] = (uint32_t)((warpN * 32 + p * 16 + brow) * 128 + bcol);

    float acc[4][4][4];
#pragma unroll
    for (int mt = 0; mt < 4; mt++)
#pragma unroll
        for (int nt = 0; nt < 4; nt++)
#pragma unroll
            for (int q = 0; q < 4; q++) acc[mt][nt][q] = 0.f;

    auto load_chunk = [&](int c, int stage) {
        const int kk = c << 6;
        const uint32_t aB = sbase + stage * STAGE_BYTES;
        const uint32_t bB = aB + A_BYTES;
#pragma unroll
        for (int i = 0; i < 4; i++)
            cp_async16(aB + dstLA[i], g_Xh + (size_t)(bm + rowLA[i]) * DIN + kk + colLA[i]);
#pragma unroll
        for (int i = 0; i < 2; i++)
            cp_async16(bB + dstLB[i], g_Wh + (size_t)(bn + rowLB[i]) * DIN + kk + colLB[i]);
    };

    // prologue: 3 chunks in flight
    load_chunk(0, 0); CP_COMMIT();
    load_chunk(1, 1); CP_COMMIT();
    load_chunk(2, 2); CP_COMMIT();

    int curStage = 0;      // stage of chunk c
    int nextStage = 3;     // stage for chunk c+3
    for (int c = 0; c < NCHUNK; c++) {
        if (c + 2 < NCHUNK)      { CP_WAIT(2); }
        else if (c + 1 < NCHUNK) { CP_WAIT(1); }
        else                     { CP_WAIT(0); }
        __syncthreads();
        if (c + 3 < NCHUNK) {
            load_chunk(c + 3, nextStage);
            CP_COMMIT();
        }

        const uint32_t aB = sbase + curStage * STAGE_BYTES;
        const uint32_t bB = aB + A_BYTES;
#pragma unroll
        for (int ks = 0; ks < 4; ks++) {
            uint32_t a[4][4];
#pragma unroll
            for (int mt = 0; mt < 4; mt++)
                ldsm_x4(a[mt], aB + swz(baseA[mt] + ks * 32));
            uint32_t b[2][4];
#pragma unroll
            for (int p = 0; p < 2; p++)
                ldsm_x4(b[p], bB + swz(baseB[p] + ks * 32));
#pragma unroll
            for (int mt = 0; mt < 4; mt++)
#pragma unroll
                for (int nt = 0; nt < 4; nt++)
                    mma_fp16(acc[mt][nt], a[mt],
                             b[nt >> 1][(nt & 1) * 2], b[nt >> 1][(nt & 1) * 2 + 1]);
        }

        curStage  = (curStage  == NSTAGE - 1) ? 0 : curStage + 1;
        nextStage = (nextStage == NSTAGE - 1) ? 0 : nextStage + 1;
    }

    // epilogue: add bias, float2 stores
    const int group = lane >> 2;
    const int tig   = lane & 3;
#pragma unroll
    for (int nt = 0; nt < 4; nt++) {
        const int col = bn + warpN * 32 + nt * 8 + tig * 2;
        const float2 bv = *(const float2*)(bias + col);
#pragma unroll
        for (int mt = 0; mt < 4; mt++) {
            const int row0 = bm + warpM * 64 + mt * 16 + group;
            float* p0 = out + (size_t)row0 * DOUT + col;
            float* p1 = out + (size_t)(row0 + 8) * DOUT + col;
            *(float2*)p0 = make_float2(acc[mt][nt][0] + bv.x, acc[mt][nt][1] + bv.y);
            *(float2*)p1 = make_float2(acc[mt][nt][2] + bv.x, acc[mt][nt][3] + bv.y);
        }
    }
}

// ---------------------------------------------------------------------------
// Launch: fused prep (with in-kernel detect) → GEMM. Two kernels total.
// ---------------------------------------------------------------------------
extern "C" void kernel_launch(void* const* d_in, const int* in_sizes, int n_in,
                              void* d_out, int out_size) {
    const float* x      = (const float*)d_in[0];
    const float* W      = (const float*)d_in[1];
    const float* b      = (const float*)d_in[2];
    const float* lora_A = (const float*)d_in[3];
    const float* lora_B = (const float*)d_in[4];
    const float* delta  = (const float*)d_in[5];
    const void*  mask   = d_in[6];

    static bool attr_done = false;
    if (!attr_done) {
        cudaFuncSetAttribute(gemm_kernel,
                             cudaFuncAttributeMaxDynamicSharedMemorySize, SMEM_TOTAL);
        attr_done = true;
    }

    // fused fold (4096 blocks, self-detecting mask dtype) + X convert (4096 blocks)
    prep_kernel<<<DOUT + MTOT / 2, 256>>>(W, lora_A, lora_B, delta, mask, x);

    dim3 grid(MTOT / BM, DOUT / BN);   // (32, 32), m fastest
    gemm_kernel<<<grid, NTHREADS, SMEM_TOTAL>>>(b, (float*)d_out);
}

// round 16
// speedup vs baseline: 1.0254x; 1.0254x over previous
#include <cuda_runtime.h>
#include <cuda_fp16.h>
#include <cstdint>

// ---------------------------------------------------------------------------
// Problem constants
// ---------------------------------------------------------------------------
#define DIN   4096
#define DOUT  4096
#define MTOT  8192
#define BK    64                          // fp16 k-elems per chunk (128 B/row)
#define NCHUNK (DIN / BK)                 // 64 — single fp16 pass
#define BM    128
#define BN    128
#define NSTAGE 3
#define STAGE_BYTES 32768                 // A 16KB + B 16KB
#define SMEM_TOTAL (NSTAGE * STAGE_BYTES) // 96 KB
static __device__ __constant__ float kScaling = 2.0f;   // 32 / rank(16)

// ---------------------------------------------------------------------------
// Device-global scratch
// ---------------------------------------------------------------------------
__device__ __half g_Xh[(size_t)MTOT * DIN];   // fp16(x)
__device__ __half g_Wh[(size_t)DOUT * DIN];   // fp16(W_eff)

// ---------------------------------------------------------------------------
// Helpers (baseline PTX only — compiles at compute_103)
// ---------------------------------------------------------------------------
__device__ __forceinline__ uint32_t smem_u32(const void* p) {
    uint32_t a;
    asm("{ .reg .u64 t; cvta.to.shared.u64 t, %1; cvt.u32.u64 %0, t; }" : "=r"(a) : "l"(p));
    return a;
}
__device__ __forceinline__ void cp_async16(uint32_t dst, const void* src) {
    asm volatile("cp.async.cg.shared.global [%0], [%1], 16;"
                 :: "r"(dst), "l"(__cvta_generic_to_global(src)));
}
#define CP_COMMIT() asm volatile("cp.async.commit_group;" ::: "memory")
#define CP_WAIT(n)  asm volatile("cp.async.wait_group %0;" :: "n"(n) : "memory")

__device__ __forceinline__ uint32_t swz(uint32_t o) { return o ^ ((o >> 3) & 0x70); }

__device__ __forceinline__ void ldsm_x4(uint32_t* r, uint32_t addr) {
    asm volatile("ldmatrix.sync.aligned.m8n8.x4.shared.b16 {%0,%1,%2,%3}, [%4];"
                 : "=r"(r[0]), "=r"(r[1]), "=r"(r[2]), "=r"(r[3]) : "r"(addr));
}
__device__ __forceinline__ void mma_fp16(float* c, const uint32_t* a,
                                         uint32_t b0, uint32_t b1) {
    asm volatile(
        "mma.sync.aligned.m16n8k16.row.col.f32.f16.f16.f32 "
        "{%0,%1,%2,%3}, {%4,%5,%6,%7}, {%8,%9}, {%0,%1,%2,%3};"
        : "+f"(c[0]), "+f"(c[1]), "+f"(c[2]), "+f"(c[3])
        : "r"(a[0]), "r"(a[1]), "r"(a[2]), "r"(a[3]), "r"(b0), "r"(b1));
}

// ---------------------------------------------------------------------------
// Fused prologue with IN-KERNEL mask dtype detection (unchanged from R13):
//   blocks [0, 4096)     : fold row o — W_eff = W + delta*mask + 2*(B@A) → fp16
//   blocks [4096, 8192)  : convert 2 rows of X → fp16
// Each fold block classifies the mask dtype from a fixed 8KB prefix
// (2048 words; P(all-zero | 1% density) ≈ 1e-9; 8KB << min 16MB buffer).
// ---------------------------------------------------------------------------
__global__ void prep_kernel(const float* __restrict__ W,
                            const float* __restrict__ lora_A,
                            const float* __restrict__ lora_B,
                            const float* __restrict__ delta,
                            const void*  __restrict__ maskp,
                            const float* __restrict__ x) {
    if (blockIdx.x < DOUT) {
        const int o = blockIdx.x;
        __shared__ float br[16];
        __shared__ int s_flags[2];
        if (threadIdx.x < 2) s_flags[threadIdx.x] = 0;
        if (threadIdx.x < 16) br[threadIdx.x] = lora_B[o * 16 + threadIdx.x] * kScaling;
        __syncthreads();

        {
            const unsigned int* mw = (const unsigned int*)maskp;
            int notF = 0, notI = 0;
#pragma unroll
            for (int it = 0; it < 8; it++) {
                unsigned int v = mw[it * 256 + threadIdx.x];
                if (v != 0u && v != 0x3F800000u) notF = 1;
                if (v > 1u)                       notI = 1;
            }
            notF = __any_sync(0xFFFFFFFFu, notF);
            notI = __any_sync(0xFFFFFFFFu, notI);
            if ((threadIdx.x & 31) == 0) {
                if (notF) atomicOr(&s_flags[0], 1);
                if (notI) atomicOr(&s_flags[1], 1);
            }
        }
        __syncthreads();
        const int mode = (s_flags[0] == 0) ? 0 : ((s_flags[1] == 0) ? 1 : 2);
        const size_t rowoff = (size_t)o * DIN;

        for (int d = threadIdx.x * 4; d < DIN; d += blockDim.x * 4) {
            float4 w4 = *(const float4*)(W + rowoff + d);
            float4 dl = *(const float4*)(delta + rowoff + d);

            float m0, m1, m2, m3;
            if (mode == 0) {
                float4 mf = *(const float4*)((const float*)maskp + rowoff + d);
                m0 = mf.x; m1 = mf.y; m2 = mf.z; m3 = mf.w;
            } else if (mode == 1) {
                int4 mi = *(const int4*)((const int*)maskp + rowoff + d);
                m0 = mi.x ? 1.f : 0.f; m1 = mi.y ? 1.f : 0.f;
                m2 = mi.z ? 1.f : 0.f; m3 = mi.w ? 1.f : 0.f;
            } else {
                uchar4 mu = *(const uchar4*)((const unsigned char*)maskp + rowoff + d);
                m0 = mu.x ? 1.f : 0.f; m1 = mu.y ? 1.f : 0.f;
                m2 = mu.z ? 1.f : 0.f; m3 = mu.w ? 1.f : 0.f;
            }

            float l0 = 0.f, l1 = 0.f, l2 = 0.f, l3 = 0.f;
#pragma unroll
            for (int r = 0; r < 16; r++) {
                float4 a4 = *(const float4*)(lora_A + (size_t)r * DIN + d);
                float s = br[r];
                l0 = fmaf(s, a4.x, l0); l1 = fmaf(s, a4.y, l1);
                l2 = fmaf(s, a4.z, l2); l3 = fmaf(s, a4.w, l3);
            }

            float v0 = w4.x + dl.x * m0 + l0;
            float v1 = w4.y + dl.y * m1 + l1;
            float v2 = w4.z + dl.z * m2 + l2;
            float v3 = w4.w + dl.w * m3 + l3;

            __half2 h01 = __floats2half2_rn(v0, v1);
            __half2 h23 = __floats2half2_rn(v2, v3);
            uint2 H;
            H.x = *(const uint32_t*)&h01;
            H.y = *(const uint32_t*)&h23;
            *(uint2*)((char*)g_Wh + (rowoff + d) * 2) = H;
        }
    } else {
        const size_t rowbase = (size_t)(blockIdx.x - DOUT) * 2 * DIN;
#pragma unroll
        for (int it = 0; it < 4; it++) {
            size_t base = rowbase + ((size_t)it * blockDim.x + threadIdx.x) * 8;
            float4 a = *(const float4*)(x + base);
            float4 b = *(const float4*)(x + base + 4);
            __half2 h0 = __floats2half2_rn(a.x, a.y);
            __half2 h1 = __floats2half2_rn(a.z, a.w);
            __half2 h2 = __floats2half2_rn(b.x, b.y);
            __half2 h3 = __floats2half2_rn(b.z, b.w);
            uint4 H;
            H.x = *(const uint32_t*)&h0; H.y = *(const uint32_t*)&h1;
            H.z = *(const uint32_t*)&h2; H.w = *(const uint32_t*)&h3;
            *(uint4*)((char*)g_Xh + base * 2) = H;
        }
    }
}

// ---------------------------------------------------------------------------
// fp16 HMMA GEMM (R13 config: 128x128, 8 warps 4m×2n, warp 32x64, 3-stage,
// 2 CTA/SM) with k-step FRAGMENT DOUBLE-BUFFERING: address tables replaced
// by inline swizzle (frees ~18 regs), spent on a second fragment set so
// ldsm of ks+1 overlaps the 16 MMAs of ks.
// ---------------------------------------------------------------------------
__global__ __launch_bounds__(256, 2)
void gemm_kernel(const float* __restrict__ bias, float* __restrict__ out) {
    extern __shared__ __align__(1024) char smem[];
    const uint32_t sbase = smem_u32(smem);
    const int tid = threadIdx.x;
    const int lane = tid & 31;
    const int wid = tid >> 5;
    const int warpM = wid >> 1;           // 0..3
    const int warpN = wid & 1;            // 0..1
    const int bm = blockIdx.x * BM;       // m fastest → W stays L2-resident
    const int bn = blockIdx.y * BN;

    // loader mapping: 4 A-slots + 4 B-slots of 16B per thread per chunk
    int rowL[4];  uint32_t dstL[4];  int colL[4];
#pragma unroll
    for (int i = 0; i < 4; i++) {
        int slot = tid + 256 * i;         // 0..1023
        rowL[i] = slot >> 3;              // 0..127
        colL[i] = (slot & 7) * 8;         // fp16 col
        dstL[i] = swz((uint32_t)(rowL[i] * 128 + (slot & 7) * 16));
    }

    // ldmatrix per-lane UNswizzled base offsets (6 regs total);
    // swizzle computed inline per use on the full offset (R4 lesson).
    const int arow  = (lane & 7) + ((lane >> 3) & 1) * 8;
    const int acol  = ((lane >> 4) & 1) * 16;           // byte
    const int brow  = (lane & 7) + ((lane >> 4) & 1) * 8;
    const int bcol  = ((lane >> 3) & 1) * 16;           // byte
    uint32_t baseA[2], baseB[4];
#pragma unroll
    for (int mt = 0; mt < 2; mt++)
        baseA[mt] = (uint32_t)((warpM * 32 + mt * 16 + arow) * 128 + acol);
#pragma unroll
    for (int p = 0; p < 4; p++)
        baseB[p] = (uint32_t)((warpN * 64 + p * 16 + brow) * 128 + bcol);

    float acc[2][8][4];
#pragma unroll
    for (int mt = 0; mt < 2; mt++)
#pragma unroll
        for (int nt = 0; nt < 8; nt++)
#pragma unroll
            for (int q = 0; q < 4; q++) acc[mt][nt][q] = 0.f;

    auto load_chunk = [&](int c, int stage) {
        const int kk = c << 6;
        const uint32_t aB = sbase + stage * STAGE_BYTES;
        const uint32_t bB = aB + 16384;
#pragma unroll
        for (int i = 0; i < 4; i++)
            cp_async16(aB + dstL[i], g_Xh + (size_t)(bm + rowL[i]) * DIN + kk + colL[i]);
#pragma unroll
        for (int i = 0; i < 4; i++)
            cp_async16(bB + dstL[i], g_Wh + (size_t)(bn + rowL[i]) * DIN + kk + colL[i]);
    };

    // prologue: 2 chunks in flight
    load_chunk(0, 0); CP_COMMIT();
    load_chunk(1, 1); CP_COMMIT();

    // fragment double buffers
    uint32_t fa[2][2][4];   // [buf][mt][4]
    uint32_t fb[2][4][4];   // [buf][p][4]

    int curStage = 0;      // stage of chunk c
    int nextStage = 2;     // stage for chunk c+2
    for (int c = 0; c < NCHUNK; c++) {
        if (c + 1 < NCHUNK) { CP_WAIT(1); } else { CP_WAIT(0); }
        __syncthreads();
        if (c + 2 < NCHUNK) {
            load_chunk(c + 2, nextStage);
            CP_COMMIT();
        }

        const uint32_t aB = sbase + curStage * STAGE_BYTES;
        const uint32_t bB = aB + 16384;

        // preload ks=0 fragments into buffer 0
#pragma unroll
        for (int mt = 0; mt < 2; mt++)
            ldsm_x4(fa[0][mt], aB + swz(baseA[mt]));
#pragma unroll
        for (int p = 0; p < 4; p++)
            ldsm_x4(fb[0][p], bB + swz(baseB[p]));

#pragma unroll
        for (int ks = 0; ks < 4; ks++) {
            const int cur = ks & 1;
            const int nxt = cur ^ 1;
            if (ks < 3) {
                // prefetch fragments for ks+1 while issuing ks MMAs
#pragma unroll
                for (int mt = 0; mt < 2; mt++)
                    ldsm_x4(fa[nxt][mt], aB + swz(baseA[mt] + (ks + 1) * 32));
#pragma unroll
                for (int p = 0; p < 4; p++)
                    ldsm_x4(fb[nxt][p], bB + swz(baseB[p] + (ks + 1) * 32));
            }
#pragma unroll
            for (int mt = 0; mt < 2; mt++)
#pragma unroll
                for (int nt = 0; nt < 8; nt++)
                    mma_fp16(acc[mt][nt], fa[cur][mt],
                             fb[cur][nt >> 1][(nt & 1) * 2],
                             fb[cur][nt >> 1][(nt & 1) * 2 + 1]);
        }

        curStage  = (curStage  == NSTAGE - 1) ? 0 : curStage + 1;
        nextStage = (nextStage == NSTAGE - 1) ? 0 : nextStage + 1;
    }

    // epilogue: add bias, float2 stores
    const int group = lane >> 2;
    const int tig   = lane & 3;
#pragma unroll
    for (int nt = 0; nt < 8; nt++) {
        const int col = bn + warpN * 64 + nt * 8 + tig * 2;
        const float2 bv = *(const float2*)(bias + col);
#pragma unroll
        for (int mt = 0; mt < 2; mt++) {
            const int row0 = bm + warpM * 32 + mt * 16 + group;
            float* p0 = out + (size_t)row0 * DOUT + col;
            float* p1 = out + (size_t)(row0 + 8) * DOUT + col;
            *(float2*)p0 = make_float2(acc[mt][nt][0] + bv.x, acc[mt][nt][1] + bv.y);
            *(float2*)p1 = make_float2(acc[mt][nt][2] + bv.x, acc[mt][nt][3] + bv.y);
        }
    }
}

// ---------------------------------------------------------------------------
// Launch: fused prep (with in-kernel detect) → GEMM. Two kernels total.
// ---------------------------------------------------------------------------
extern "C" void kernel_launch(void* const* d_in, const int* in_sizes, int n_in,
                              void* d_out, int out_size) {
    const float* x      = (const float*)d_in[0];
    const float* W      = (const float*)d_in[1];
    const float* b      = (const float*)d_in[2];
    const float* lora_A = (const float*)d_in[3];
    const float* lora_B = (const float*)d_in[4];
    const float* delta  = (const float*)d_in[5];
    const void*  mask   = d_in[6];

    static bool attr_done = false;
    if (!attr_done) {
        cudaFuncSetAttribute(gemm_kernel,
                             cudaFuncAttributeMaxDynamicSharedMemorySize, SMEM_TOTAL);
        attr_done = true;
    }

    // fused fold (4096 blocks, self-detecting mask dtype) + X convert (4096 blocks)
    prep_kernel<<<DOUT + MTOT / 2, 256>>>(W, lora_A, lora_B, delta, mask, x);

    dim3 grid(MTOT / BM, DOUT / BN);   // (64, 32), m fastest
    gemm_kernel<<<grid, 256, SMEM_TOTAL>>>(b, (float*)d_out);
}